// round 12
// baseline (speedup 1.0000x reference)
#include <cuda_runtime.h>
#include <cuda_fp16.h>
#include <cstdint>
#include <math.h>

#define DIM     2048
#define TWO_DIM 4096
#define NH      16
#define HD      128
#define BATCH   4
#define SEQT    2048
#define M_TOK   8192   // BATCH*SEQT

// ---------------- scratch (__device__ globals: allocation-free rule) -------
__device__ __half g_enc_h[(size_t)M_TOK * DIM];
__device__ __half g_enc_l[(size_t)M_TOK * DIM];
__device__ __half g_dec_h[(size_t)M_TOK * DIM];
__device__ __half g_dec_l[(size_t)M_TOK * DIM];
__device__ __half g_kv   [(size_t)M_TOK * TWO_DIM];   // K|V single fp16
__device__ __half g_q_h  [(size_t)M_TOK * DIM];
__device__ __half g_q_l  [(size_t)M_TOK * DIM];
__device__ __half g_ao_h [(size_t)M_TOK * DIM];
__device__ __half g_ao_l [(size_t)M_TOK * DIM];
// weights transposed to [N, K], single fp16
__device__ __half g_wkv[(size_t)TWO_DIM * DIM];
__device__ __half g_wq [(size_t)DIM * DIM];
__device__ __half g_wo [(size_t)DIM * DIM];

// ---------------- helpers ---------------------------------------------------
__device__ __forceinline__ uint32_t smem_u32(const void* p) {
    uint32_t a;
    asm("{ .reg .u64 t; cvta.to.shared.u64 t, %1; cvt.u32.u64 %0, t; }" : "=r"(a) : "l"(p));
    return a;
}
__device__ __forceinline__ void cp_async16(uint32_t dst, const void* src) {
    asm volatile("cp.async.cg.shared.global [%0], [%1], 16;" :: "r"(dst), "l"(src));
}
#define CP_COMMIT() asm volatile("cp.async.commit_group;" ::: "memory")

__device__ __forceinline__ void mma16816(float* d, const uint32_t* a, const uint32_t* b) {
    asm volatile(
        "mma.sync.aligned.m16n8k16.row.col.f32.f16.f16.f32 "
        "{%0,%1,%2,%3}, {%4,%5,%6,%7}, {%8,%9}, {%0,%1,%2,%3};\n"
        : "+f"(d[0]), "+f"(d[1]), "+f"(d[2]), "+f"(d[3])
        : "r"(a[0]), "r"(a[1]), "r"(a[2]), "r"(a[3]), "r"(b[0]), "r"(b[1]));
}
__device__ __forceinline__ void ldsm4(uint32_t* r, uint32_t saddr) {
    asm volatile("ldmatrix.sync.aligned.m8n8.x4.shared.b16 {%0,%1,%2,%3}, [%4];"
        : "=r"(r[0]), "=r"(r[1]), "=r"(r[2]), "=r"(r[3]) : "r"(saddr));
}
__device__ __forceinline__ void ldsm4t(uint32_t* r, uint32_t saddr) {
    asm volatile("ldmatrix.sync.aligned.m8n8.x4.trans.shared.b16 {%0,%1,%2,%3}, [%4];"
        : "=r"(r[0]), "=r"(r[1]), "=r"(r[2]), "=r"(r[3]) : "r"(saddr));
}
__device__ __forceinline__ uint32_t pack_hi_h(float v0, float v1, float& r0, float& r1) {
    __half2 h = __floats2half2_rn(v0, v1);
    r0 = v0 - __half2float(__low2half(h));
    r1 = v1 - __half2float(__high2half(h));
    return *reinterpret_cast<uint32_t*>(&h);
}
__device__ __forceinline__ uint32_t pack_h2(float v0, float v1) {
    __half2 h = __floats2half2_rn(v0, v1);
    return *reinterpret_cast<uint32_t*>(&h);
}

// ---------------- conversion kernels ---------------------------------------
__global__ __launch_bounds__(256)
void split_kernel(const float* __restrict__ x, __half* __restrict__ h,
                  __half* __restrict__ l, int n4) {
    int i = blockIdx.x * blockDim.x + threadIdx.x;
    if (i >= n4) return;
    float4 v = ((const float4*)x)[i];
    __half h0 = __float2half_rn(v.x), h1 = __float2half_rn(v.y);
    __half h2 = __float2half_rn(v.z), h3 = __float2half_rn(v.w);
    __half l0 = __float2half_rn(v.x - __half2float(h0));
    __half l1 = __float2half_rn(v.y - __half2float(h1));
    __half l2 = __float2half_rn(v.z - __half2float(h2));
    __half l3 = __float2half_rn(v.w - __half2float(h3));
    ((__half2*)h)[2 * i]     = __halves2half2(h0, h1);
    ((__half2*)h)[2 * i + 1] = __halves2half2(h2, h3);
    ((__half2*)l)[2 * i]     = __halves2half2(l0, l1);
    ((__half2*)l)[2 * i + 1] = __halves2half2(l2, l3);
}

// W[K,N] fp32 -> WT [N,K] fp16 (single)
__global__ __launch_bounds__(256)
void roundT_kernel(const float* __restrict__ W, __half* __restrict__ h, int K, int N) {
    __shared__ float t[32][33];
    int n0 = blockIdx.x * 32, k0 = blockIdx.y * 32;
    int tx = threadIdx.x & 31, ty = threadIdx.x >> 5;
    #pragma unroll
    for (int i = 0; i < 32; i += 8)
        t[ty + i][tx] = W[(size_t)(k0 + ty + i) * N + n0 + tx];
    __syncthreads();
    #pragma unroll
    for (int i = 0; i < 32; i += 8)
        h[(size_t)(n0 + ty + i) * K + k0 + tx] = __float2half_rn(t[tx][ty + i]);
}

// ---------------- mma.sync 2-product fp16 GEMM ------------------------------
// C = (Ah+Al) @ Bt^T + bias.  Bt [N,K] single fp16.
// CTA 128x256, 8 warps (2m x 4n), warp 64x64.  BK=32, 3-stage single-sync pipe.
// Smem rows: 80 B stride (40 halfs), 16B-aligned, conflict-free.
#define BK        32
#define ROWQ      40
#define A_ELEMS   (128 * ROWQ)            // one A limb: 5120 halfs = 10240 B
#define B_ELEMS   (256 * ROWQ)            // B: 10240 halfs = 20480 B
#define STAGE_BYTES (2 * A_ELEMS * 2 + B_ELEMS * 2)   // Ah, Al, B = 40960 B
#define GT_STAGES 3
#define GT_SMEM   (GT_STAGES * STAGE_BYTES)   // 122880

__device__ __forceinline__ void load_chunk(uint32_t sbase,
    const __half* Ah, const __half* Al, const __half* B, int K, int kt, int tid)
{
    // 512 logical rows (Ah 0..127, Al 128..255, B 256..511), uniform 80B stride.
    #pragma unroll
    for (int i = 0; i < 8; i++) {
        int idx = i * 256 + tid;
        int r = idx >> 2, seg = idx & 3;
        uint32_t dst = sbase + (uint32_t)(r * 80 + seg * 16);
        const __half* src;
        if (r < 128)      src = Ah + (size_t)r * K;
        else if (r < 256) src = Al + (size_t)(r - 128) * K;
        else              src = B  + (size_t)(r - 256) * K;
        cp_async16(dst, src + kt + seg * 8);
    }
}

__global__ __launch_bounds__(256, 1)
void gemm_tc(const __half* __restrict__ Ah, const __half* __restrict__ Al,
             const __half* __restrict__ Bt,
             const float* __restrict__ bias, float scale,
             float* __restrict__ Cf,
             __half* __restrict__ Ch, __half* __restrict__ Cl,
             int mode, int M, int N, int K)
{
    extern __shared__ __align__(16) char sm_g[];
    uint32_t sbase = smem_u32(sm_g);
    int tid = threadIdx.x, wid = tid >> 5, lid = tid & 31;
    int g = lid >> 2, t = lid & 3;
    int wm = (wid & 1) * 64;        // 2 m-tiles of 64
    int wn = (wid >> 1) * 64;       // 4 n-tiles of 64
    int m0 = blockIdx.y * 128, n0 = blockIdx.x * 256;

    const __half* A_h = Ah + (size_t)m0 * K;
    const __half* A_l = Al + (size_t)m0 * K;
    const __half* B_p = Bt + (size_t)n0 * K;

    float acc[4][8][4];
    #pragma unroll
    for (int i = 0; i < 4; i++)
        #pragma unroll
        for (int j = 0; j < 8; j++)
            #pragma unroll
            for (int r = 0; r < 4; r++) acc[i][j][r] = 0.f;

    const int NCH = K / BK;

    load_chunk(sbase,               A_h, A_l, B_p, K, 0,  tid);
    CP_COMMIT();
    load_chunk(sbase + STAGE_BYTES, A_h, A_l, B_p, K, BK, tid);
    CP_COMMIT();

    // ldmatrix lane addressing
    int arow  = lid & 15;
    int akoff = ((lid >> 4) & 1) * 8;
    int brow  = ((lid >> 4) & 1) * 8 + (lid & 7);
    int bkoff = ((lid >> 3) & 1) * 8;

    int ld_stage = 2;
    for (int c = 0; c < NCH; c++) {
        if (c == NCH - 1) asm volatile("cp.async.wait_group 0;" ::: "memory");
        else              asm volatile("cp.async.wait_group 1;" ::: "memory");
        __syncthreads();

        if (c + 2 < NCH) {
            load_chunk(sbase + (uint32_t)ld_stage * STAGE_BYTES,
                       A_h, A_l, B_p, K, (c + 2) * BK, tid);
            CP_COMMIT();
            ld_stage = (ld_stage + 1 == GT_STAGES) ? 0 : ld_stage + 1;
        }

        uint32_t stb = sbase + (uint32_t)(c % GT_STAGES) * STAGE_BYTES;
        uint32_t aAh = stb;
        uint32_t aAl = stb + A_ELEMS * 2;
        uint32_t aB  = stb + A_ELEMS * 4;

        #pragma unroll
        for (int ks = 0; ks < BK; ks += 16) {
            uint32_t ah[4][4], al[4][4], bb[4][4];
            #pragma unroll
            for (int mi = 0; mi < 4; mi++) {
                uint32_t off = (uint32_t)((wm + mi * 16 + arow) * ROWQ + ks + akoff) * 2;
                ldsm4(ah[mi], aAh + off);
                ldsm4(al[mi], aAl + off);
            }
            #pragma unroll
            for (int p = 0; p < 4; p++) {
                uint32_t off = (uint32_t)((wn + p * 16 + brow) * ROWQ + ks + bkoff) * 2;
                ldsm4(bb[p], aB + off);
            }
            #pragma unroll
            for (int mi = 0; mi < 4; mi++)
                #pragma unroll
                for (int p = 0; p < 4; p++)
                    #pragma unroll
                    for (int h2 = 0; h2 < 2; h2++) {
                        mma16816(acc[mi][2 * p + h2], ah[mi], &bb[p][2 * h2]);
                        mma16816(acc[mi][2 * p + h2], al[mi], &bb[p][2 * h2]);
                    }
        }
    }

    #pragma unroll
    for (int nj = 0; nj < 8; nj++) {
        int col = n0 + wn + nj * 8 + t * 2;
        float b0 = bias[col], b1 = bias[col + 1];
        #pragma unroll
        for (int mi = 0; mi < 4; mi++) {
            int row = m0 + wm + mi * 16 + g;
            float v0 = acc[mi][nj][0] + b0, v1 = acc[mi][nj][1] + b1;
            float v2 = acc[mi][nj][2] + b0, v3 = acc[mi][nj][3] + b1;
            if (mode == 0) {
                *(float2*)(Cf + (size_t)row * N + col)       = make_float2(v0, v1);
                *(float2*)(Cf + (size_t)(row + 8) * N + col) = make_float2(v2, v3);
            } else if (mode == 2) {
                *(uint32_t*)(Ch + (size_t)row * N + col)       = pack_h2(v0, v1);
                *(uint32_t*)(Ch + (size_t)(row + 8) * N + col) = pack_h2(v2, v3);
            } else {
                v0 *= scale; v1 *= scale; v2 *= scale; v3 *= scale;
                float r0, r1, r2, r3;
                uint32_t h01 = pack_hi_h(v0, v1, r0, r1);
                uint32_t h23 = pack_hi_h(v2, v3, r2, r3);
                *(uint32_t*)(Ch + (size_t)row * N + col)       = h01;
                *(uint32_t*)(Ch + (size_t)(row + 8) * N + col) = h23;
                *(uint32_t*)(Cl + (size_t)row * N + col)       = pack_h2(r0, r1);
                *(uint32_t*)(Cl + (size_t)(row + 8) * N + col) = pack_h2(r2, r3);
            }
        }
    }
}

// ---------------- 2-product fp16 flash attention (unchanged from R6) -------
#define AT_ROWP 136
#define AT_QTILE (128 * AT_ROWP)
#define AT_KTILE (64 * AT_ROWP)
#define AT_Q_OFF   0
#define AT_QL_OFF  AT_QTILE
#define AT_K_OFF(s)  (2 * AT_QTILE + 2 * (s) * AT_KTILE)
#define AT_V_OFF(s)  (AT_K_OFF(s) + AT_KTILE)
#define AT_SMEM    ((2 * AT_QTILE + 4 * AT_KTILE) * 2)   // 139264 B

__device__ __forceinline__ void at_load_kv(uint32_t sb, const __half* KV,
                                           int b, int h, int kb, int s, int tid)
{
    const __half* src = KV + (size_t)(b * SEQT + kb * 64) * TWO_DIM + h * HD;
    #pragma unroll
    for (int i = 0; i < 4; i++) {
        int idx = i * 256 + tid;
        int r = idx >> 4, seg = idx & 15;
        uint32_t doff = (uint32_t)(r * AT_ROWP + seg * 8) * 2;
        size_t goff = (size_t)r * TWO_DIM + seg * 8;
        cp_async16(sb + AT_K_OFF(s) * 2 + doff, src + goff);
        cp_async16(sb + AT_V_OFF(s) * 2 + doff, src + DIM + goff);
    }
}

__global__ __launch_bounds__(256)
void attn_mma(const __half* __restrict__ Qh, const __half* __restrict__ Ql,
              const __half* __restrict__ KV,
              __half* __restrict__ Oh, __half* __restrict__ Ol)
{
    extern __shared__ __align__(16) char sab[];
    uint32_t sb = smem_u32(sab);
    int tid = threadIdx.x, wid = tid >> 5, lid = tid & 31;
    int g = lid >> 2, t = lid & 3;
    int qb = blockIdx.x, h = blockIdx.y, b = blockIdx.z;
    int q0 = qb * 128;

    {
        const __half* srcH = Qh + (size_t)(b * SEQT + q0) * DIM + h * HD;
        const __half* srcL = Ql + (size_t)(b * SEQT + q0) * DIM + h * HD;
        #pragma unroll
        for (int i = 0; i < 8; i++) {
            int idx = i * 256 + tid;
            int r = idx >> 4, seg = idx & 15;
            uint32_t doff = (uint32_t)(r * AT_ROWP + seg * 8) * 2;
            size_t goff = (size_t)r * DIM + seg * 8;
            cp_async16(sb + AT_Q_OFF * 2 + doff,  srcH + goff);
            cp_async16(sb + AT_QL_OFF * 2 + doff, srcL + goff);
        }
        CP_COMMIT();
    }
    at_load_kv(sb, KV, b, h, 0, 0, tid);
    CP_COMMIT();

    float m0 = -1e30f, m1 = -1e30f, l0 = 0.f, l1 = 0.f;
    float po[16][4];
    #pragma unroll
    for (int i = 0; i < 16; i++)
        #pragma unroll
        for (int r = 0; r < 4; r++) po[i][r] = 0.f;

    int qrow  = lid & 15;
    int qkoff = ((lid >> 4) & 1) * 8;
    int krow  = ((lid >> 4) & 1) * 8 + (lid & 7);
    int kkoff = ((lid >> 3) & 1) * 8;
    uint32_t vrow  = (uint32_t)(lid & 15);
    uint32_t vcolx = (lid & 16) ? 8u : 0u;

    int nkb = 2 * qb + 2;
    for (int kb = 0; kb < nkb; kb++) {
        int s = kb & 1;
        asm volatile("cp.async.wait_group 0;" ::: "memory");
        __syncthreads();

        if (kb + 1 < nkb) { at_load_kv(sb, KV, b, h, kb + 1, s ^ 1, tid); CP_COMMIT(); }

        uint32_t aQh = sb + AT_Q_OFF * 2;
        uint32_t aQl = sb + AT_QL_OFF * 2;
        uint32_t aK  = sb + AT_K_OFF(s) * 2;
        uint32_t aV  = sb + AT_V_OFF(s) * 2;

        float sacc[8][4];
        #pragma unroll
        for (int nj = 0; nj < 8; nj++)
            #pragma unroll
            for (int r = 0; r < 4; r++) sacc[nj][r] = 0.f;

        #pragma unroll
        for (int kc = 0; kc < 8; kc++) {
            uint32_t ah[4], al[4];
            uint32_t qoff = (uint32_t)((wid * 16 + qrow) * AT_ROWP + kc * 16 + qkoff) * 2;
            ldsm4(ah, aQh + qoff);
            ldsm4(al, aQl + qoff);
            #pragma unroll
            for (int p = 0; p < 4; p++) {
                uint32_t kf[4];
                uint32_t koff = (uint32_t)((p * 16 + krow) * AT_ROWP + kc * 16 + kkoff) * 2;
                ldsm4(kf, aK + koff);
                #pragma unroll
                for (int h2 = 0; h2 < 2; h2++) {
                    mma16816(sacc[2 * p + h2], ah, &kf[2 * h2]);
                    mma16816(sacc[2 * p + h2], al, &kf[2 * h2]);
                }
            }
        }

        int ig0 = q0 + wid * 16 + g;
        int ig1 = ig0 + 8;
        if (kb * 64 + 63 > q0 + wid * 16) {
            #pragma unroll
            for (int nj = 0; nj < 8; nj++) {
                int c0 = kb * 64 + nj * 8 + t * 2;
                if (c0     > ig0) sacc[nj][0] = -1e30f;
                if (c0 + 1 > ig0) sacc[nj][1] = -1e30f;
                if (c0     > ig1) sacc[nj][2] = -1e30f;
                if (c0 + 1 > ig1) sacc[nj][3] = -1e30f;
            }
        }

        float rmax0 = -1e30f, rmax1 = -1e30f;
        #pragma unroll
        for (int nj = 0; nj < 8; nj++) {
            rmax0 = fmaxf(rmax0, fmaxf(sacc[nj][0], sacc[nj][1]));
            rmax1 = fmaxf(rmax1, fmaxf(sacc[nj][2], sacc[nj][3]));
        }
        rmax0 = fmaxf(rmax0, __shfl_xor_sync(0xffffffffu, rmax0, 1));
        rmax0 = fmaxf(rmax0, __shfl_xor_sync(0xffffffffu, rmax0, 2));
        rmax1 = fmaxf(rmax1, __shfl_xor_sync(0xffffffffu, rmax1, 1));
        rmax1 = fmaxf(rmax1, __shfl_xor_sync(0xffffffffu, rmax1, 2));
        float mn0 = fmaxf(m0, rmax0), mn1 = fmaxf(m1, rmax1);
        float alpha0 = __expf(m0 - mn0), alpha1 = __expf(m1 - mn1);
        float rs0 = 0.f, rs1 = 0.f;
        #pragma unroll
        for (int nj = 0; nj < 8; nj++) {
            float p0 = __expf(sacc[nj][0] - mn0);
            float p1 = __expf(sacc[nj][1] - mn0);
            float p2 = __expf(sacc[nj][2] - mn1);
            float p3 = __expf(sacc[nj][3] - mn1);
            sacc[nj][0] = p0; sacc[nj][1] = p1; sacc[nj][2] = p2; sacc[nj][3] = p3;
            rs0 += p0 + p1;
            rs1 += p2 + p3;
        }
        rs0 += __shfl_xor_sync(0xffffffffu, rs0, 1);
        rs0 += __shfl_xor_sync(0xffffffffu, rs0, 2);
        rs1 += __shfl_xor_sync(0xffffffffu, rs1, 1);
        rs1 += __shfl_xor_sync(0xffffffffu, rs1, 2);
        l0 = l0 * alpha0 + rs0;
        l1 = l1 * alpha1 + rs1;
        m0 = mn0; m1 = mn1;

        #pragma unroll
        for (int dj = 0; dj < 16; dj++) {
            po[dj][0] *= alpha0; po[dj][1] *= alpha0;
            po[dj][2] *= alpha1; po[dj][3] *= alpha1;
        }

        #pragma unroll
        for (int kc2 = 0; kc2 < 4; kc2++) {
            uint32_t ph[4], pl[4];
            {
                float r0, r1;
                ph[0] = pack_hi_h(sacc[2 * kc2][0],     sacc[2 * kc2][1],     r0, r1);
                pl[0] = pack_h2(r0, r1);
                ph[1] = pack_hi_h(sacc[2 * kc2][2],     sacc[2 * kc2][3],     r0, r1);
                pl[1] = pack_h2(r0, r1);
                ph[2] = pack_hi_h(sacc[2 * kc2 + 1][0], sacc[2 * kc2 + 1][1], r0, r1);
                pl[2] = pack_h2(r0, r1);
                ph[3] = pack_hi_h(sacc[2 * kc2 + 1][2], sacc[2 * kc2 + 1][3], r0, r1);
                pl[3] = pack_h2(r0, r1);
            }
            #pragma unroll
            for (int ds = 0; ds < 8; ds++) {
                uint32_t vh[4];
                uint32_t aoff = ((kc2 * 16 + vrow) * AT_ROWP + ds * 16 + vcolx) * 2;
                ldsm4t(vh, aV + aoff);
                mma16816(po[2 * ds],     ph, &vh[0]);
                mma16816(po[2 * ds],     pl, &vh[0]);
                mma16816(po[2 * ds + 1], ph, &vh[2]);
                mma16816(po[2 * ds + 1], pl, &vh[2]);
            }
        }
    }

    float inv0 = 1.f / l0, inv1 = 1.f / l1;
    size_t tok0 = (size_t)(b * SEQT + q0 + wid * 16 + g);
    size_t tok1 = tok0 + 8;
    #pragma unroll
    for (int dj = 0; dj < 16; dj++) {
        int col = h * HD + dj * 8 + t * 2;
        float v0 = po[dj][0] * inv0, v1 = po[dj][1] * inv0;
        float v2 = po[dj][2] * inv1, v3 = po[dj][3] * inv1;
        float r0, r1, r2, r3;
        uint32_t h01 = pack_hi_h(v0, v1, r0, r1);
        uint32_t h23 = pack_hi_h(v2, v3, r2, r3);
        *(uint32_t*)(Oh + tok0 * DIM + col) = h01;
        *(uint32_t*)(Oh + tok1 * DIM + col) = h23;
        *(uint32_t*)(Ol + tok0 * DIM + col) = pack_h2(r0, r1);
        *(uint32_t*)(Ol + tok1 * DIM + col) = pack_h2(r2, r3);
    }
}

// ---------------------------------------------------------------------------
extern "C" void kernel_launch(void* const* d_in, const int* in_sizes, int n_in,
                              void* d_out, int out_size) {
    const float* enc = (const float*)d_in[0];
    const float* dec = (const float*)d_in[1];
    const float* Wkv = (const float*)d_in[2];
    const float* bkv = (const float*)d_in[3];
    const float* Wq  = (const float*)d_in[4];
    const float* bq  = (const float*)d_in[5];
    const float* Wo  = (const float*)d_in[6];
    const float* bo  = (const float*)d_in[7];
    float* out = (float*)d_out;

    __half *eh, *el, *dh, *dl, *kv, *qh, *ql, *aoh, *aol, *wkv, *wq, *wo;
    cudaGetSymbolAddress((void**)&eh,  g_enc_h);  cudaGetSymbolAddress((void**)&el,  g_enc_l);
    cudaGetSymbolAddress((void**)&dh,  g_dec_h);  cudaGetSymbolAddress((void**)&dl,  g_dec_l);
    cudaGetSymbolAddress((void**)&kv,  g_kv);
    cudaGetSymbolAddress((void**)&qh,  g_q_h);    cudaGetSymbolAddress((void**)&ql,  g_q_l);
    cudaGetSymbolAddress((void**)&aoh, g_ao_h);   cudaGetSymbolAddress((void**)&aol, g_ao_l);
    cudaGetSymbolAddress((void**)&wkv, g_wkv);
    cudaGetSymbolAddress((void**)&wq,  g_wq);
    cudaGetSymbolAddress((void**)&wo,  g_wo);

    cudaFuncSetAttribute(gemm_tc, cudaFuncAttributeMaxDynamicSharedMemorySize, GT_SMEM);
    cudaFuncSetAttribute(attn_mma, cudaFuncAttributeMaxDynamicSharedMemorySize, AT_SMEM);

    int n4_act = (M_TOK * DIM) / 4;
    const float qscale = 0.08838834764831845f;   // 1/sqrt(128)

    split_kernel<<<(n4_act + 255) / 256, 256>>>(enc, eh, el, n4_act);
    split_kernel<<<(n4_act + 255) / 256, 256>>>(dec, dh, dl, n4_act);
    roundT_kernel<<<dim3(TWO_DIM / 32, DIM / 32), 256>>>(Wkv, wkv, DIM, TWO_DIM);
    roundT_kernel<<<dim3(DIM / 32,     DIM / 32), 256>>>(Wq,  wq,  DIM, DIM);
    roundT_kernel<<<dim3(DIM / 32,     DIM / 32), 256>>>(Wo,  wo,  DIM, DIM);

    // KV projection -> single fp16 (mode 2)
    gemm_tc<<<dim3(TWO_DIM / 256, M_TOK / 128), 256, GT_SMEM>>>(
        eh, el, wkv, bkv, 1.0f, nullptr, kv, nullptr, 2, M_TOK, TWO_DIM, DIM);
    // Q projection -> fp16 hi/lo, pre-scaled (mode 1)
    gemm_tc<<<dim3(DIM / 256, M_TOK / 128), 256, GT_SMEM>>>(
        dh, dl, wq, bq, qscale, nullptr, qh, ql, 1, M_TOK, DIM, DIM);

    // attention -> fp16 hi/lo
    attn_mma<<<dim3(SEQT / 128, NH, BATCH), 256, AT_SMEM>>>(qh, ql, kv, aoh, aol);

    // O projection -> fp32 out (mode 0)
    gemm_tc<<<dim3(DIM / 256, M_TOK / 128), 256, GT_SMEM>>>(
        aoh, aol, wo, bo, 1.0f, out, nullptr, nullptr, 0, M_TOK, DIM, DIM);
}

// round 13
// speedup vs baseline: 1.2928x; 1.2928x over previous
#include <cuda_runtime.h>
#include <cuda_fp16.h>
#include <cstdint>
#include <math.h>

#define DIM     2048
#define TWO_DIM 4096
#define NH      16
#define HD      128
#define BATCH   4
#define SEQT    2048
#define M_TOK   8192   // BATCH*SEQT

// ---------------- scratch (__device__ globals: allocation-free rule) -------
__device__ __half g_enc [(size_t)M_TOK * DIM];       // single fp16 activations
__device__ __half g_dec [(size_t)M_TOK * DIM];
__device__ __half g_kv  [(size_t)M_TOK * TWO_DIM];   // K|V single fp16
__device__ __half g_q_h [(size_t)M_TOK * DIM];       // Q stays hi/lo (softmax-sensitive)
__device__ __half g_q_l [(size_t)M_TOK * DIM];
__device__ __half g_ao  [(size_t)M_TOK * DIM];       // attention out, single fp16
// weights transposed to [N, K], single fp16
__device__ __half g_wkv[(size_t)TWO_DIM * DIM];
__device__ __half g_wq [(size_t)DIM * DIM];
__device__ __half g_wo [(size_t)DIM * DIM];

// ---------------- helpers ---------------------------------------------------
__device__ __forceinline__ uint32_t smem_u32(const void* p) {
    uint32_t a;
    asm("{ .reg .u64 t; cvta.to.shared.u64 t, %1; cvt.u32.u64 %0, t; }" : "=r"(a) : "l"(p));
    return a;
}
__device__ __forceinline__ void cp_async16(uint32_t dst, const void* src) {
    asm volatile("cp.async.cg.shared.global [%0], [%1], 16;" :: "r"(dst), "l"(src));
}
#define CP_COMMIT() asm volatile("cp.async.commit_group;" ::: "memory")

__device__ __forceinline__ void mma16816(float* d, const uint32_t* a, const uint32_t* b) {
    asm volatile(
        "mma.sync.aligned.m16n8k16.row.col.f32.f16.f16.f32 "
        "{%0,%1,%2,%3}, {%4,%5,%6,%7}, {%8,%9}, {%0,%1,%2,%3};\n"
        : "+f"(d[0]), "+f"(d[1]), "+f"(d[2]), "+f"(d[3])
        : "r"(a[0]), "r"(a[1]), "r"(a[2]), "r"(a[3]), "r"(b[0]), "r"(b[1]));
}
__device__ __forceinline__ void ldsm4(uint32_t* r, uint32_t saddr) {
    asm volatile("ldmatrix.sync.aligned.m8n8.x4.shared.b16 {%0,%1,%2,%3}, [%4];"
        : "=r"(r[0]), "=r"(r[1]), "=r"(r[2]), "=r"(r[3]) : "r"(saddr));
}
__device__ __forceinline__ void ldsm4t(uint32_t* r, uint32_t saddr) {
    asm volatile("ldmatrix.sync.aligned.m8n8.x4.trans.shared.b16 {%0,%1,%2,%3}, [%4];"
        : "=r"(r[0]), "=r"(r[1]), "=r"(r[2]), "=r"(r[3]) : "r"(saddr));
}
__device__ __forceinline__ uint32_t pack_hi_h(float v0, float v1, float& r0, float& r1) {
    __half2 h = __floats2half2_rn(v0, v1);
    r0 = v0 - __half2float(__low2half(h));
    r1 = v1 - __half2float(__high2half(h));
    return *reinterpret_cast<uint32_t*>(&h);
}
__device__ __forceinline__ uint32_t pack_h2(float v0, float v1) {
    __half2 h = __floats2half2_rn(v0, v1);
    return *reinterpret_cast<uint32_t*>(&h);
}

// ---------------- conversion kernels ---------------------------------------
__global__ __launch_bounds__(256)
void round_kernel(const float* __restrict__ x, __half* __restrict__ h, int n4) {
    int i = blockIdx.x * blockDim.x + threadIdx.x;
    if (i >= n4) return;
    float4 v = ((const float4*)x)[i];
    ((__half2*)h)[2 * i]     = __floats2half2_rn(v.x, v.y);
    ((__half2*)h)[2 * i + 1] = __floats2half2_rn(v.z, v.w);
}

// W[K,N] fp32 -> WT [N,K] fp16 (single)
__global__ __launch_bounds__(256)
void roundT_kernel(const float* __restrict__ W, __half* __restrict__ h, int K, int N) {
    __shared__ float t[32][33];
    int n0 = blockIdx.x * 32, k0 = blockIdx.y * 32;
    int tx = threadIdx.x & 31, ty = threadIdx.x >> 5;
    #pragma unroll
    for (int i = 0; i < 32; i += 8)
        t[ty + i][tx] = W[(size_t)(k0 + ty + i) * N + n0 + tx];
    __syncthreads();
    #pragma unroll
    for (int i = 0; i < 32; i += 8)
        h[(size_t)(n0 + ty + i) * K + k0 + tx] = __float2half_rn(t[tx][ty + i]);
}

// ---------------- mma.sync single-product fp16 GEMM -------------------------
// C = A @ Bt^T + bias.  A, Bt single fp16 ([M,K] and [N,K]).
// CTA 128x128, 8 warps (2m x 4n), warp 64x32.  BK=32, 3-stage single-sync pipe.
#define BK        32
#define ROWQ      40
#define A_ELEMS   (128 * ROWQ)            // 5120 halfs = 10240 B per array
#define STAGE_BYTES (2 * A_ELEMS * 2)     // A, B = 20480 B
#define GT_STAGES 3
#define GT_SMEM   (GT_STAGES * STAGE_BYTES)   // 61440

__device__ __forceinline__ void load_chunk(uint32_t sbase,
    const __half* A, const __half* B, int K, int kt, int tid)
{
    // 256 logical rows (A 0..127, B 128..255), uniform 80B stride.
    #pragma unroll
    for (int i = 0; i < 4; i++) {
        int idx = i * 256 + tid;
        int r = idx >> 2, seg = idx & 3;
        uint32_t dst = sbase + (uint32_t)(r * 80 + seg * 16);
        const __half* src = (r < 128) ? (A + (size_t)r * K)
                                      : (B + (size_t)(r - 128) * K);
        cp_async16(dst, src + kt + seg * 8);
    }
}

__global__ __launch_bounds__(256, 1)
void gemm_tc(const __half* __restrict__ A, const __half* __restrict__ Bt,
             const float* __restrict__ bias, float scale,
             float* __restrict__ Cf,
             __half* __restrict__ Ch, __half* __restrict__ Cl,
             int mode, int M, int N, int K)
{
    extern __shared__ __align__(16) char sm_g[];
    uint32_t sbase = smem_u32(sm_g);
    int tid = threadIdx.x, wid = tid >> 5, lid = tid & 31;
    int g = lid >> 2, t = lid & 3;
    int wm = (wid & 1) * 64;
    int wn = (wid >> 1) * 32;
    int m0 = blockIdx.y * 128, n0 = blockIdx.x * 128;

    const __half* A_p = A  + (size_t)m0 * K;
    const __half* B_p = Bt + (size_t)n0 * K;

    float acc[4][4][4];
    #pragma unroll
    for (int i = 0; i < 4; i++)
        #pragma unroll
        for (int j = 0; j < 4; j++)
            #pragma unroll
            for (int r = 0; r < 4; r++) acc[i][j][r] = 0.f;

    const int NCH = K / BK;

    load_chunk(sbase,               A_p, B_p, K, 0,  tid);
    CP_COMMIT();
    load_chunk(sbase + STAGE_BYTES, A_p, B_p, K, BK, tid);
    CP_COMMIT();

    // ldmatrix lane addressing
    int arow  = lid & 15;
    int akoff = ((lid >> 4) & 1) * 8;
    int brow  = ((lid >> 4) & 1) * 8 + (lid & 7);
    int bkoff = ((lid >> 3) & 1) * 8;

    int ld_stage = 2;
    for (int c = 0; c < NCH; c++) {
        if (c == NCH - 1) asm volatile("cp.async.wait_group 0;" ::: "memory");
        else              asm volatile("cp.async.wait_group 1;" ::: "memory");
        __syncthreads();

        if (c + 2 < NCH) {
            load_chunk(sbase + (uint32_t)ld_stage * STAGE_BYTES,
                       A_p, B_p, K, (c + 2) * BK, tid);
            CP_COMMIT();
            ld_stage = (ld_stage + 1 == GT_STAGES) ? 0 : ld_stage + 1;
        }

        uint32_t stb = sbase + (uint32_t)(c % GT_STAGES) * STAGE_BYTES;
        uint32_t aA = stb;
        uint32_t aB = stb + A_ELEMS * 2;

        #pragma unroll
        for (int ks = 0; ks < BK; ks += 16) {
            uint32_t ah[4][4], bb[2][4];
            #pragma unroll
            for (int mi = 0; mi < 4; mi++) {
                uint32_t off = (uint32_t)((wm + mi * 16 + arow) * ROWQ + ks + akoff) * 2;
                ldsm4(ah[mi], aA + off);
            }
            #pragma unroll
            for (int p = 0; p < 2; p++) {
                uint32_t off = (uint32_t)((wn + p * 16 + brow) * ROWQ + ks + bkoff) * 2;
                ldsm4(bb[p], aB + off);
            }
            #pragma unroll
            for (int mi = 0; mi < 4; mi++)
                #pragma unroll
                for (int p = 0; p < 2; p++)
                    #pragma unroll
                    for (int h2 = 0; h2 < 2; h2++)
                        mma16816(acc[mi][2 * p + h2], ah[mi], &bb[p][2 * h2]);
        }
    }

    #pragma unroll
    for (int nj = 0; nj < 4; nj++) {
        int col = n0 + wn + nj * 8 + t * 2;
        float b0 = bias[col], b1 = bias[col + 1];
        #pragma unroll
        for (int mi = 0; mi < 4; mi++) {
            int row = m0 + wm + mi * 16 + g;
            float v0 = acc[mi][nj][0] + b0, v1 = acc[mi][nj][1] + b1;
            float v2 = acc[mi][nj][2] + b0, v3 = acc[mi][nj][3] + b1;
            if (mode == 0) {
                *(float2*)(Cf + (size_t)row * N + col)       = make_float2(v0, v1);
                *(float2*)(Cf + (size_t)(row + 8) * N + col) = make_float2(v2, v3);
            } else if (mode == 2) {
                *(uint32_t*)(Ch + (size_t)row * N + col)       = pack_h2(v0, v1);
                *(uint32_t*)(Ch + (size_t)(row + 8) * N + col) = pack_h2(v2, v3);
            } else {
                v0 *= scale; v1 *= scale; v2 *= scale; v3 *= scale;
                float r0, r1, r2, r3;
                uint32_t h01 = pack_hi_h(v0, v1, r0, r1);
                uint32_t h23 = pack_hi_h(v2, v3, r2, r3);
                *(uint32_t*)(Ch + (size_t)row * N + col)       = h01;
                *(uint32_t*)(Ch + (size_t)(row + 8) * N + col) = h23;
                *(uint32_t*)(Cl + (size_t)row * N + col)       = pack_h2(r0, r1);
                *(uint32_t*)(Cl + (size_t)(row + 8) * N + col) = pack_h2(r2, r3);
            }
        }
    }
}

// ---------------- 2-product fp16 flash attention (R6, single-fp16 output) --
#define AT_ROWP 136
#define AT_QTILE (128 * AT_ROWP)
#define AT_KTILE (64 * AT_ROWP)
#define AT_Q_OFF   0
#define AT_QL_OFF  AT_QTILE
#define AT_K_OFF(s)  (2 * AT_QTILE + 2 * (s) * AT_KTILE)
#define AT_V_OFF(s)  (AT_K_OFF(s) + AT_KTILE)
#define AT_SMEM    ((2 * AT_QTILE + 4 * AT_KTILE) * 2)   // 139264 B

__device__ __forceinline__ void at_load_kv(uint32_t sb, const __half* KV,
                                           int b, int h, int kb, int s, int tid)
{
    const __half* src = KV + (size_t)(b * SEQT + kb * 64) * TWO_DIM + h * HD;
    #pragma unroll
    for (int i = 0; i < 4; i++) {
        int idx = i * 256 + tid;
        int r = idx >> 4, seg = idx & 15;
        uint32_t doff = (uint32_t)(r * AT_ROWP + seg * 8) * 2;
        size_t goff = (size_t)r * TWO_DIM + seg * 8;
        cp_async16(sb + AT_K_OFF(s) * 2 + doff, src + goff);
        cp_async16(sb + AT_V_OFF(s) * 2 + doff, src + DIM + goff);
    }
}

__global__ __launch_bounds__(256)
void attn_mma(const __half* __restrict__ Qh, const __half* __restrict__ Ql,
              const __half* __restrict__ KV, __half* __restrict__ O)
{
    extern __shared__ __align__(16) char sab[];
    uint32_t sb = smem_u32(sab);
    int tid = threadIdx.x, wid = tid >> 5, lid = tid & 31;
    int g = lid >> 2, t = lid & 3;
    int qb = blockIdx.x, h = blockIdx.y, b = blockIdx.z;
    int q0 = qb * 128;

    {
        const __half* srcH = Qh + (size_t)(b * SEQT + q0) * DIM + h * HD;
        const __half* srcL = Ql + (size_t)(b * SEQT + q0) * DIM + h * HD;
        #pragma unroll
        for (int i = 0; i < 8; i++) {
            int idx = i * 256 + tid;
            int r = idx >> 4, seg = idx & 15;
            uint32_t doff = (uint32_t)(r * AT_ROWP + seg * 8) * 2;
            size_t goff = (size_t)r * DIM + seg * 8;
            cp_async16(sb + AT_Q_OFF * 2 + doff,  srcH + goff);
            cp_async16(sb + AT_QL_OFF * 2 + doff, srcL + goff);
        }
        CP_COMMIT();
    }
    at_load_kv(sb, KV, b, h, 0, 0, tid);
    CP_COMMIT();

    float m0 = -1e30f, m1 = -1e30f, l0 = 0.f, l1 = 0.f;
    float po[16][4];
    #pragma unroll
    for (int i = 0; i < 16; i++)
        #pragma unroll
        for (int r = 0; r < 4; r++) po[i][r] = 0.f;

    int qrow  = lid & 15;
    int qkoff = ((lid >> 4) & 1) * 8;
    int krow  = ((lid >> 4) & 1) * 8 + (lid & 7);
    int kkoff = ((lid >> 3) & 1) * 8;
    uint32_t vrow  = (uint32_t)(lid & 15);
    uint32_t vcolx = (lid & 16) ? 8u : 0u;

    int nkb = 2 * qb + 2;
    for (int kb = 0; kb < nkb; kb++) {
        int s = kb & 1;
        asm volatile("cp.async.wait_group 0;" ::: "memory");
        __syncthreads();

        if (kb + 1 < nkb) { at_load_kv(sb, KV, b, h, kb + 1, s ^ 1, tid); CP_COMMIT(); }

        uint32_t aQh = sb + AT_Q_OFF * 2;
        uint32_t aQl = sb + AT_QL_OFF * 2;
        uint32_t aK  = sb + AT_K_OFF(s) * 2;
        uint32_t aV  = sb + AT_V_OFF(s) * 2;

        float sacc[8][4];
        #pragma unroll
        for (int nj = 0; nj < 8; nj++)
            #pragma unroll
            for (int r = 0; r < 4; r++) sacc[nj][r] = 0.f;

        #pragma unroll
        for (int kc = 0; kc < 8; kc++) {
            uint32_t ah[4], al[4];
            uint32_t qoff = (uint32_t)((wid * 16 + qrow) * AT_ROWP + kc * 16 + qkoff) * 2;
            ldsm4(ah, aQh + qoff);
            ldsm4(al, aQl + qoff);
            #pragma unroll
            for (int p = 0; p < 4; p++) {
                uint32_t kf[4];
                uint32_t koff = (uint32_t)((p * 16 + krow) * AT_ROWP + kc * 16 + kkoff) * 2;
                ldsm4(kf, aK + koff);
                #pragma unroll
                for (int h2 = 0; h2 < 2; h2++) {
                    mma16816(sacc[2 * p + h2], ah, &kf[2 * h2]);
                    mma16816(sacc[2 * p + h2], al, &kf[2 * h2]);
                }
            }
        }

        int ig0 = q0 + wid * 16 + g;
        int ig1 = ig0 + 8;
        if (kb * 64 + 63 > q0 + wid * 16) {
            #pragma unroll
            for (int nj = 0; nj < 8; nj++) {
                int c0 = kb * 64 + nj * 8 + t * 2;
                if (c0     > ig0) sacc[nj][0] = -1e30f;
                if (c0 + 1 > ig0) sacc[nj][1] = -1e30f;
                if (c0     > ig1) sacc[nj][2] = -1e30f;
                if (c0 + 1 > ig1) sacc[nj][3] = -1e30f;
            }
        }

        float rmax0 = -1e30f, rmax1 = -1e30f;
        #pragma unroll
        for (int nj = 0; nj < 8; nj++) {
            rmax0 = fmaxf(rmax0, fmaxf(sacc[nj][0], sacc[nj][1]));
            rmax1 = fmaxf(rmax1, fmaxf(sacc[nj][2], sacc[nj][3]));
        }
        rmax0 = fmaxf(rmax0, __shfl_xor_sync(0xffffffffu, rmax0, 1));
        rmax0 = fmaxf(rmax0, __shfl_xor_sync(0xffffffffu, rmax0, 2));
        rmax1 = fmaxf(rmax1, __shfl_xor_sync(0xffffffffu, rmax1, 1));
        rmax1 = fmaxf(rmax1, __shfl_xor_sync(0xffffffffu, rmax1, 2));
        float mn0 = fmaxf(m0, rmax0), mn1 = fmaxf(m1, rmax1);
        float alpha0 = __expf(m0 - mn0), alpha1 = __expf(m1 - mn1);
        float rs0 = 0.f, rs1 = 0.f;
        #pragma unroll
        for (int nj = 0; nj < 8; nj++) {
            float p0 = __expf(sacc[nj][0] - mn0);
            float p1 = __expf(sacc[nj][1] - mn0);
            float p2 = __expf(sacc[nj][2] - mn1);
            float p3 = __expf(sacc[nj][3] - mn1);
            sacc[nj][0] = p0; sacc[nj][1] = p1; sacc[nj][2] = p2; sacc[nj][3] = p3;
            rs0 += p0 + p1;
            rs1 += p2 + p3;
        }
        rs0 += __shfl_xor_sync(0xffffffffu, rs0, 1);
        rs0 += __shfl_xor_sync(0xffffffffu, rs0, 2);
        rs1 += __shfl_xor_sync(0xffffffffu, rs1, 1);
        rs1 += __shfl_xor_sync(0xffffffffu, rs1, 2);
        l0 = l0 * alpha0 + rs0;
        l1 = l1 * alpha1 + rs1;
        m0 = mn0; m1 = mn1;

        #pragma unroll
        for (int dj = 0; dj < 16; dj++) {
            po[dj][0] *= alpha0; po[dj][1] *= alpha0;
            po[dj][2] *= alpha1; po[dj][3] *= alpha1;
        }

        #pragma unroll
        for (int kc2 = 0; kc2 < 4; kc2++) {
            uint32_t ph[4], pl[4];
            {
                float r0, r1;
                ph[0] = pack_hi_h(sacc[2 * kc2][0],     sacc[2 * kc2][1],     r0, r1);
                pl[0] = pack_h2(r0, r1);
                ph[1] = pack_hi_h(sacc[2 * kc2][2],     sacc[2 * kc2][3],     r0, r1);
                pl[1] = pack_h2(r0, r1);
                ph[2] = pack_hi_h(sacc[2 * kc2 + 1][0], sacc[2 * kc2 + 1][1], r0, r1);
                pl[2] = pack_h2(r0, r1);
                ph[3] = pack_hi_h(sacc[2 * kc2 + 1][2], sacc[2 * kc2 + 1][3], r0, r1);
                pl[3] = pack_h2(r0, r1);
            }
            #pragma unroll
            for (int ds = 0; ds < 8; ds++) {
                uint32_t vh[4];
                uint32_t aoff = ((kc2 * 16 + vrow) * AT_ROWP + ds * 16 + vcolx) * 2;
                ldsm4t(vh, aV + aoff);
                mma16816(po[2 * ds],     ph, &vh[0]);
                mma16816(po[2 * ds],     pl, &vh[0]);
                mma16816(po[2 * ds + 1], ph, &vh[2]);
                mma16816(po[2 * ds + 1], pl, &vh[2]);
            }
        }
    }

    // epilogue: normalize, round to single fp16, store
    float inv0 = 1.f / l0, inv1 = 1.f / l1;
    size_t tok0 = (size_t)(b * SEQT + q0 + wid * 16 + g);
    size_t tok1 = tok0 + 8;
    #pragma unroll
    for (int dj = 0; dj < 16; dj++) {
        int col = h * HD + dj * 8 + t * 2;
        *(uint32_t*)(O + tok0 * DIM + col) = pack_h2(po[dj][0] * inv0, po[dj][1] * inv0);
        *(uint32_t*)(O + tok1 * DIM + col) = pack_h2(po[dj][2] * inv1, po[dj][3] * inv1);
    }
}

// ---------------------------------------------------------------------------
extern "C" void kernel_launch(void* const* d_in, const int* in_sizes, int n_in,
                              void* d_out, int out_size) {
    const float* enc = (const float*)d_in[0];
    const float* dec = (const float*)d_in[1];
    const float* Wkv = (const float*)d_in[2];
    const float* bkv = (const float*)d_in[3];
    const float* Wq  = (const float*)d_in[4];
    const float* bq  = (const float*)d_in[5];
    const float* Wo  = (const float*)d_in[6];
    const float* bo  = (const float*)d_in[7];
    float* out = (float*)d_out;

    __half *eh, *dh, *kv, *qh, *ql, *ao, *wkv, *wq, *wo;
    cudaGetSymbolAddress((void**)&eh,  g_enc);
    cudaGetSymbolAddress((void**)&dh,  g_dec);
    cudaGetSymbolAddress((void**)&kv,  g_kv);
    cudaGetSymbolAddress((void**)&qh,  g_q_h);
    cudaGetSymbolAddress((void**)&ql,  g_q_l);
    cudaGetSymbolAddress((void**)&ao,  g_ao);
    cudaGetSymbolAddress((void**)&wkv, g_wkv);
    cudaGetSymbolAddress((void**)&wq,  g_wq);
    cudaGetSymbolAddress((void**)&wo,  g_wo);

    cudaFuncSetAttribute(gemm_tc, cudaFuncAttributeMaxDynamicSharedMemorySize, GT_SMEM);
    cudaFuncSetAttribute(attn_mma, cudaFuncAttributeMaxDynamicSharedMemorySize, AT_SMEM);

    int n4_act = (M_TOK * DIM) / 4;
    const float qscale = 0.08838834764831845f;   // 1/sqrt(128)

    round_kernel<<<(n4_act + 255) / 256, 256>>>(enc, eh, n4_act);
    round_kernel<<<(n4_act + 255) / 256, 256>>>(dec, dh, n4_act);
    roundT_kernel<<<dim3(TWO_DIM / 32, DIM / 32), 256>>>(Wkv, wkv, DIM, TWO_DIM);
    roundT_kernel<<<dim3(DIM / 32,     DIM / 32), 256>>>(Wq,  wq,  DIM, DIM);
    roundT_kernel<<<dim3(DIM / 32,     DIM / 32), 256>>>(Wo,  wo,  DIM, DIM);

    // KV projection -> single fp16 (mode 2)
    gemm_tc<<<dim3(TWO_DIM / 128, M_TOK / 128), 256, GT_SMEM>>>(
        eh, wkv, bkv, 1.0f, nullptr, kv, nullptr, 2, M_TOK, TWO_DIM, DIM);
    // Q projection -> fp16 hi/lo, pre-scaled (mode 1)
    gemm_tc<<<dim3(DIM / 128, M_TOK / 128), 256, GT_SMEM>>>(
        dh, wq, bq, qscale, nullptr, qh, ql, 1, M_TOK, DIM, DIM);

    // attention -> single fp16
    attn_mma<<<dim3(SEQT / 128, NH, BATCH), 256, AT_SMEM>>>(qh, ql, kv, ao);

    // O projection -> fp32 out (mode 0)
    gemm_tc<<<dim3(DIM / 128, M_TOK / 128), 256, GT_SMEM>>>(
        ao, wo, bo, 1.0f, out, nullptr, nullptr, 0, M_TOK, DIM, DIM);
}

// round 14
// speedup vs baseline: 1.7052x; 1.3189x over previous
#include <cuda_runtime.h>
#include <cuda_fp16.h>
#include <cstdint>
#include <math.h>

#define DIM     2048
#define TWO_DIM 4096
#define NH      16
#define HD      128
#define BATCH   4
#define SEQT    2048
#define M_TOK   8192   // BATCH*SEQT

// ---------------- scratch (__device__ globals: allocation-free rule) -------
__device__ __half g_enc [(size_t)M_TOK * DIM];       // single fp16 activations
__device__ __half g_dec [(size_t)M_TOK * DIM];
__device__ __half g_kv  [(size_t)M_TOK * TWO_DIM];   // K|V single fp16
__device__ __half g_q_h [(size_t)M_TOK * DIM];       // Q stays hi/lo (softmax-sensitive)
__device__ __half g_q_l [(size_t)M_TOK * DIM];
__device__ __half g_ao  [(size_t)M_TOK * DIM];       // attention out, single fp16
// weights transposed to [N, K], single fp16
__device__ __half g_wkv[(size_t)TWO_DIM * DIM];
__device__ __half g_wq [(size_t)DIM * DIM];
__device__ __half g_wo [(size_t)DIM * DIM];

// ---------------- helpers ---------------------------------------------------
__device__ __forceinline__ uint32_t smem_u32(const void* p) {
    uint32_t a;
    asm("{ .reg .u64 t; cvta.to.shared.u64 t, %1; cvt.u32.u64 %0, t; }" : "=r"(a) : "l"(p));
    return a;
}
__device__ __forceinline__ void cp_async16(uint32_t dst, const void* src) {
    asm volatile("cp.async.cg.shared.global [%0], [%1], 16;" :: "r"(dst), "l"(src));
}
#define CP_COMMIT() asm volatile("cp.async.commit_group;" ::: "memory")

__device__ __forceinline__ void mma16816(float* d, const uint32_t* a, const uint32_t* b) {
    asm volatile(
        "mma.sync.aligned.m16n8k16.row.col.f32.f16.f16.f32 "
        "{%0,%1,%2,%3}, {%4,%5,%6,%7}, {%8,%9}, {%0,%1,%2,%3};\n"
        : "+f"(d[0]), "+f"(d[1]), "+f"(d[2]), "+f"(d[3])
        : "r"(a[0]), "r"(a[1]), "r"(a[2]), "r"(a[3]), "r"(b[0]), "r"(b[1]));
}
__device__ __forceinline__ void ldsm4(uint32_t* r, uint32_t saddr) {
    asm volatile("ldmatrix.sync.aligned.m8n8.x4.shared.b16 {%0,%1,%2,%3}, [%4];"
        : "=r"(r[0]), "=r"(r[1]), "=r"(r[2]), "=r"(r[3]) : "r"(saddr));
}
__device__ __forceinline__ void ldsm4t(uint32_t* r, uint32_t saddr) {
    asm volatile("ldmatrix.sync.aligned.m8n8.x4.trans.shared.b16 {%0,%1,%2,%3}, [%4];"
        : "=r"(r[0]), "=r"(r[1]), "=r"(r[2]), "=r"(r[3]) : "r"(saddr));
}
__device__ __forceinline__ uint32_t pack_hi_h(float v0, float v1, float& r0, float& r1) {
    __half2 h = __floats2half2_rn(v0, v1);
    r0 = v0 - __half2float(__low2half(h));
    r1 = v1 - __half2float(__high2half(h));
    return *reinterpret_cast<uint32_t*>(&h);
}
__device__ __forceinline__ uint32_t pack_h2(float v0, float v1) {
    __half2 h = __floats2half2_rn(v0, v1);
    return *reinterpret_cast<uint32_t*>(&h);
}

// ---------------- conversion kernels ---------------------------------------
__global__ __launch_bounds__(256)
void round_kernel(const float* __restrict__ x, __half* __restrict__ h, int n4) {
    int i = blockIdx.x * blockDim.x + threadIdx.x;
    if (i >= n4) return;
    float4 v = ((const float4*)x)[i];
    ((__half2*)h)[2 * i]     = __floats2half2_rn(v.x, v.y);
    ((__half2*)h)[2 * i + 1] = __floats2half2_rn(v.z, v.w);
}

// W[K,N] fp32 -> WT [N,K] fp16 (single)
__global__ __launch_bounds__(256)
void roundT_kernel(const float* __restrict__ W, __half* __restrict__ h, int K, int N) {
    __shared__ float t[32][33];
    int n0 = blockIdx.x * 32, k0 = blockIdx.y * 32;
    int tx = threadIdx.x & 31, ty = threadIdx.x >> 5;
    #pragma unroll
    for (int i = 0; i < 32; i += 8)
        t[ty + i][tx] = W[(size_t)(k0 + ty + i) * N + n0 + tx];
    __syncthreads();
    #pragma unroll
    for (int i = 0; i < 32; i += 8)
        h[(size_t)(n0 + ty + i) * K + k0 + tx] = __float2half_rn(t[tx][ty + i]);
}

// ---------------- mma.sync single-product fp16 GEMM -------------------------
// C = A @ Bt^T + bias.  A, Bt single fp16 ([M,K] and [N,K]).
// CTA 128x128, 8 warps (2m x 4n), warp 64x32.  BK=32, 3-stage single-sync pipe.
// __launch_bounds__(256,2): 2 CTAs/SM (smem 2x60KB, regs capped 128) to test
// whether the ~12cyc/HMMA rate is a latency artifact vs a hw issue floor.
#define BK        32
#define ROWQ      40
#define A_ELEMS   (128 * ROWQ)            // 5120 halfs = 10240 B per array
#define STAGE_BYTES (2 * A_ELEMS * 2)     // A, B = 20480 B
#define GT_STAGES 3
#define GT_SMEM   (GT_STAGES * STAGE_BYTES)   // 61440

__device__ __forceinline__ void load_chunk(uint32_t sbase,
    const __half* A, const __half* B, int K, int kt, int tid)
{
    // 256 logical rows (A 0..127, B 128..255), uniform 80B stride.
    #pragma unroll
    for (int i = 0; i < 4; i++) {
        int idx = i * 256 + tid;
        int r = idx >> 2, seg = idx & 3;
        uint32_t dst = sbase + (uint32_t)(r * 80 + seg * 16);
        const __half* src = (r < 128) ? (A + (size_t)r * K)
                                      : (B + (size_t)(r - 128) * K);
        cp_async16(dst, src + kt + seg * 8);
    }
}

__global__ __launch_bounds__(256, 2)
void gemm_tc(const __half* __restrict__ A, const __half* __restrict__ Bt,
             const float* __restrict__ bias, float scale,
             float* __restrict__ Cf,
             __half* __restrict__ Ch, __half* __restrict__ Cl,
             int mode, int M, int N, int K)
{
    extern __shared__ __align__(16) char sm_g[];
    uint32_t sbase = smem_u32(sm_g);
    int tid = threadIdx.x, wid = tid >> 5, lid = tid & 31;
    int g = lid >> 2, t = lid & 3;
    int wm = (wid & 1) * 64;
    int wn = (wid >> 1) * 32;
    int m0 = blockIdx.y * 128, n0 = blockIdx.x * 128;

    const __half* A_p = A  + (size_t)m0 * K;
    const __half* B_p = Bt + (size_t)n0 * K;

    float acc[4][4][4];
    #pragma unroll
    for (int i = 0; i < 4; i++)
        #pragma unroll
        for (int j = 0; j < 4; j++)
            #pragma unroll
            for (int r = 0; r < 4; r++) acc[i][j][r] = 0.f;

    const int NCH = K / BK;

    load_chunk(sbase,               A_p, B_p, K, 0,  tid);
    CP_COMMIT();
    load_chunk(sbase + STAGE_BYTES, A_p, B_p, K, BK, tid);
    CP_COMMIT();

    // ldmatrix lane addressing
    int arow  = lid & 15;
    int akoff = ((lid >> 4) & 1) * 8;
    int brow  = ((lid >> 4) & 1) * 8 + (lid & 7);
    int bkoff = ((lid >> 3) & 1) * 8;

    int ld_stage = 2;
    for (int c = 0; c < NCH; c++) {
        if (c == NCH - 1) asm volatile("cp.async.wait_group 0;" ::: "memory");
        else              asm volatile("cp.async.wait_group 1;" ::: "memory");
        __syncthreads();

        if (c + 2 < NCH) {
            load_chunk(sbase + (uint32_t)ld_stage * STAGE_BYTES,
                       A_p, B_p, K, (c + 2) * BK, tid);
            CP_COMMIT();
            ld_stage = (ld_stage + 1 == GT_STAGES) ? 0 : ld_stage + 1;
        }

        uint32_t stb = sbase + (uint32_t)(c % GT_STAGES) * STAGE_BYTES;
        uint32_t aA = stb;
        uint32_t aB = stb + A_ELEMS * 2;

        #pragma unroll
        for (int ks = 0; ks < BK; ks += 16) {
            uint32_t ah[4][4], bb[2][4];
            #pragma unroll
            for (int mi = 0; mi < 4; mi++) {
                uint32_t off = (uint32_t)((wm + mi * 16 + arow) * ROWQ + ks + akoff) * 2;
                ldsm4(ah[mi], aA + off);
            }
            #pragma unroll
            for (int p = 0; p < 2; p++) {
                uint32_t off = (uint32_t)((wn + p * 16 + brow) * ROWQ + ks + bkoff) * 2;
                ldsm4(bb[p], aB + off);
            }
            #pragma unroll
            for (int mi = 0; mi < 4; mi++)
                #pragma unroll
                for (int p = 0; p < 2; p++)
                    #pragma unroll
                    for (int h2 = 0; h2 < 2; h2++)
                        mma16816(acc[mi][2 * p + h2], ah[mi], &bb[p][2 * h2]);
        }
    }

    #pragma unroll
    for (int nj = 0; nj < 4; nj++) {
        int col = n0 + wn + nj * 8 + t * 2;
        float b0 = bias[col], b1 = bias[col + 1];
        #pragma unroll
        for (int mi = 0; mi < 4; mi++) {
            int row = m0 + wm + mi * 16 + g;
            float v0 = acc[mi][nj][0] + b0, v1 = acc[mi][nj][1] + b1;
            float v2 = acc[mi][nj][2] + b0, v3 = acc[mi][nj][3] + b1;
            if (mode == 0) {
                *(float2*)(Cf + (size_t)row * N + col)       = make_float2(v0, v1);
                *(float2*)(Cf + (size_t)(row + 8) * N + col) = make_float2(v2, v3);
            } else if (mode == 2) {
                *(uint32_t*)(Ch + (size_t)row * N + col)       = pack_h2(v0, v1);
                *(uint32_t*)(Ch + (size_t)(row + 8) * N + col) = pack_h2(v2, v3);
            } else {
                v0 *= scale; v1 *= scale; v2 *= scale; v3 *= scale;
                float r0, r1, r2, r3;
                uint32_t h01 = pack_hi_h(v0, v1, r0, r1);
                uint32_t h23 = pack_hi_h(v2, v3, r2, r3);
                *(uint32_t*)(Ch + (size_t)row * N + col)       = h01;
                *(uint32_t*)(Ch + (size_t)(row + 8) * N + col) = h23;
                *(uint32_t*)(Cl + (size_t)row * N + col)       = pack_h2(r0, r1);
                *(uint32_t*)(Cl + (size_t)(row + 8) * N + col) = pack_h2(r2, r3);
            }
        }
    }
}

// ---------------- fp16 flash attention (2-limb Q, single-limb P) -----------
#define AT_ROWP 136
#define AT_QTILE (128 * AT_ROWP)
#define AT_KTILE (64 * AT_ROWP)
#define AT_Q_OFF   0
#define AT_QL_OFF  AT_QTILE
#define AT_K_OFF(s)  (2 * AT_QTILE + 2 * (s) * AT_KTILE)
#define AT_V_OFF(s)  (AT_K_OFF(s) + AT_KTILE)
#define AT_SMEM    ((2 * AT_QTILE + 4 * AT_KTILE) * 2)   // 139264 B

__device__ __forceinline__ void at_load_kv(uint32_t sb, const __half* KV,
                                           int b, int h, int kb, int s, int tid)
{
    const __half* src = KV + (size_t)(b * SEQT + kb * 64) * TWO_DIM + h * HD;
    #pragma unroll
    for (int i = 0; i < 4; i++) {
        int idx = i * 256 + tid;
        int r = idx >> 4, seg = idx & 15;
        uint32_t doff = (uint32_t)(r * AT_ROWP + seg * 8) * 2;
        size_t goff = (size_t)r * TWO_DIM + seg * 8;
        cp_async16(sb + AT_K_OFF(s) * 2 + doff, src + goff);
        cp_async16(sb + AT_V_OFF(s) * 2 + doff, src + DIM + goff);
    }
}

__global__ __launch_bounds__(256)
void attn_mma(const __half* __restrict__ Qh, const __half* __restrict__ Ql,
              const __half* __restrict__ KV, __half* __restrict__ O)
{
    extern __shared__ __align__(16) char sab[];
    uint32_t sb = smem_u32(sab);
    int tid = threadIdx.x, wid = tid >> 5, lid = tid & 31;
    int g = lid >> 2, t = lid & 3;
    int qb = blockIdx.x, h = blockIdx.y, b = blockIdx.z;
    int q0 = qb * 128;

    {
        const __half* srcH = Qh + (size_t)(b * SEQT + q0) * DIM + h * HD;
        const __half* srcL = Ql + (size_t)(b * SEQT + q0) * DIM + h * HD;
        #pragma unroll
        for (int i = 0; i < 8; i++) {
            int idx = i * 256 + tid;
            int r = idx >> 4, seg = idx & 15;
            uint32_t doff = (uint32_t)(r * AT_ROWP + seg * 8) * 2;
            size_t goff = (size_t)r * DIM + seg * 8;
            cp_async16(sb + AT_Q_OFF * 2 + doff,  srcH + goff);
            cp_async16(sb + AT_QL_OFF * 2 + doff, srcL + goff);
        }
        CP_COMMIT();
    }
    at_load_kv(sb, KV, b, h, 0, 0, tid);
    CP_COMMIT();

    float m0 = -1e30f, m1 = -1e30f, l0 = 0.f, l1 = 0.f;
    float po[16][4];
    #pragma unroll
    for (int i = 0; i < 16; i++)
        #pragma unroll
        for (int r = 0; r < 4; r++) po[i][r] = 0.f;

    int qrow  = lid & 15;
    int qkoff = ((lid >> 4) & 1) * 8;
    int krow  = ((lid >> 4) & 1) * 8 + (lid & 7);
    int kkoff = ((lid >> 3) & 1) * 8;
    uint32_t vrow  = (uint32_t)(lid & 15);
    uint32_t vcolx = (lid & 16) ? 8u : 0u;

    int nkb = 2 * qb + 2;
    for (int kb = 0; kb < nkb; kb++) {
        int s = kb & 1;
        asm volatile("cp.async.wait_group 0;" ::: "memory");
        __syncthreads();

        if (kb + 1 < nkb) { at_load_kv(sb, KV, b, h, kb + 1, s ^ 1, tid); CP_COMMIT(); }

        uint32_t aQh = sb + AT_Q_OFF * 2;
        uint32_t aQl = sb + AT_QL_OFF * 2;
        uint32_t aK  = sb + AT_K_OFF(s) * 2;
        uint32_t aV  = sb + AT_V_OFF(s) * 2;

        float sacc[8][4];
        #pragma unroll
        for (int nj = 0; nj < 8; nj++)
            #pragma unroll
            for (int r = 0; r < 4; r++) sacc[nj][r] = 0.f;

        #pragma unroll
        for (int kc = 0; kc < 8; kc++) {
            uint32_t ah[4], al[4];
            uint32_t qoff = (uint32_t)((wid * 16 + qrow) * AT_ROWP + kc * 16 + qkoff) * 2;
            ldsm4(ah, aQh + qoff);
            ldsm4(al, aQl + qoff);
            #pragma unroll
            for (int p = 0; p < 4; p++) {
                uint32_t kf[4];
                uint32_t koff = (uint32_t)((p * 16 + krow) * AT_ROWP + kc * 16 + kkoff) * 2;
                ldsm4(kf, aK + koff);
                #pragma unroll
                for (int h2 = 0; h2 < 2; h2++) {
                    mma16816(sacc[2 * p + h2], ah, &kf[2 * h2]);
                    mma16816(sacc[2 * p + h2], al, &kf[2 * h2]);
                }
            }
        }

        int ig0 = q0 + wid * 16 + g;
        int ig1 = ig0 + 8;
        if (kb * 64 + 63 > q0 + wid * 16) {
            #pragma unroll
            for (int nj = 0; nj < 8; nj++) {
                int c0 = kb * 64 + nj * 8 + t * 2;
                if (c0     > ig0) sacc[nj][0] = -1e30f;
                if (c0 + 1 > ig0) sacc[nj][1] = -1e30f;
                if (c0     > ig1) sacc[nj][2] = -1e30f;
                if (c0 + 1 > ig1) sacc[nj][3] = -1e30f;
            }
        }

        float rmax0 = -1e30f, rmax1 = -1e30f;
        #pragma unroll
        for (int nj = 0; nj < 8; nj++) {
            rmax0 = fmaxf(rmax0, fmaxf(sacc[nj][0], sacc[nj][1]));
            rmax1 = fmaxf(rmax1, fmaxf(sacc[nj][2], sacc[nj][3]));
        }
        rmax0 = fmaxf(rmax0, __shfl_xor_sync(0xffffffffu, rmax0, 1));
        rmax0 = fmaxf(rmax0, __shfl_xor_sync(0xffffffffu, rmax0, 2));
        rmax1 = fmaxf(rmax1, __shfl_xor_sync(0xffffffffu, rmax1, 1));
        rmax1 = fmaxf(rmax1, __shfl_xor_sync(0xffffffffu, rmax1, 2));
        float mn0 = fmaxf(m0, rmax0), mn1 = fmaxf(m1, rmax1);
        float alpha0 = __expf(m0 - mn0), alpha1 = __expf(m1 - mn1);
        float rs0 = 0.f, rs1 = 0.f;
        #pragma unroll
        for (int nj = 0; nj < 8; nj++) {
            float p0 = __expf(sacc[nj][0] - mn0);
            float p1 = __expf(sacc[nj][1] - mn0);
            float p2 = __expf(sacc[nj][2] - mn1);
            float p3 = __expf(sacc[nj][3] - mn1);
            sacc[nj][0] = p0; sacc[nj][1] = p1; sacc[nj][2] = p2; sacc[nj][3] = p3;
            rs0 += p0 + p1;
            rs1 += p2 + p3;
        }
        rs0 += __shfl_xor_sync(0xffffffffu, rs0, 1);
        rs0 += __shfl_xor_sync(0xffffffffu, rs0, 2);
        rs1 += __shfl_xor_sync(0xffffffffu, rs1, 1);
        rs1 += __shfl_xor_sync(0xffffffffu, rs1, 2);
        l0 = l0 * alpha0 + rs0;
        l1 = l1 * alpha1 + rs1;
        m0 = mn0; m1 = mn1;

        #pragma unroll
        for (int dj = 0; dj < 16; dj++) {
            po[dj][0] *= alpha0; po[dj][1] *= alpha0;
            po[dj][2] *= alpha1; po[dj][3] *= alpha1;
        }

        // ---- O += P @ V, single-fp16 P ----
        #pragma unroll
        for (int kc2 = 0; kc2 < 4; kc2++) {
            uint32_t ph[4];
            ph[0] = pack_h2(sacc[2 * kc2][0],     sacc[2 * kc2][1]);
            ph[1] = pack_h2(sacc[2 * kc2][2],     sacc[2 * kc2][3]);
            ph[2] = pack_h2(sacc[2 * kc2 + 1][0], sacc[2 * kc2 + 1][1]);
            ph[3] = pack_h2(sacc[2 * kc2 + 1][2], sacc[2 * kc2 + 1][3]);
            #pragma unroll
            for (int ds = 0; ds < 8; ds++) {
                uint32_t vh[4];
                uint32_t aoff = ((kc2 * 16 + vrow) * AT_ROWP + ds * 16 + vcolx) * 2;
                ldsm4t(vh, aV + aoff);
                mma16816(po[2 * ds],     ph, &vh[0]);
                mma16816(po[2 * ds + 1], ph, &vh[2]);
            }
        }
    }

    // epilogue: normalize, round to single fp16, store
    float inv0 = 1.f / l0, inv1 = 1.f / l1;
    size_t tok0 = (size_t)(b * SEQT + q0 + wid * 16 + g);
    size_t tok1 = tok0 + 8;
    #pragma unroll
    for (int dj = 0; dj < 16; dj++) {
        int col = h * HD + dj * 8 + t * 2;
        *(uint32_t*)(O + tok0 * DIM + col) = pack_h2(po[dj][0] * inv0, po[dj][1] * inv0);
        *(uint32_t*)(O + tok1 * DIM + col) = pack_h2(po[dj][2] * inv1, po[dj][3] * inv1);
    }
}

// ---------------------------------------------------------------------------
extern "C" void kernel_launch(void* const* d_in, const int* in_sizes, int n_in,
                              void* d_out, int out_size) {
    const float* enc = (const float*)d_in[0];
    const float* dec = (const float*)d_in[1];
    const float* Wkv = (const float*)d_in[2];
    const float* bkv = (const float*)d_in[3];
    const float* Wq  = (const float*)d_in[4];
    const float* bq  = (const float*)d_in[5];
    const float* Wo  = (const float*)d_in[6];
    const float* bo  = (const float*)d_in[7];
    float* out = (float*)d_out;

    __half *eh, *dh, *kv, *qh, *ql, *ao, *wkv, *wq, *wo;
    cudaGetSymbolAddress((void**)&eh,  g_enc);
    cudaGetSymbolAddress((void**)&dh,  g_dec);
    cudaGetSymbolAddress((void**)&kv,  g_kv);
    cudaGetSymbolAddress((void**)&qh,  g_q_h);
    cudaGetSymbolAddress((void**)&ql,  g_q_l);
    cudaGetSymbolAddress((void**)&ao,  g_ao);
    cudaGetSymbolAddress((void**)&wkv, g_wkv);
    cudaGetSymbolAddress((void**)&wq,  g_wq);
    cudaGetSymbolAddress((void**)&wo,  g_wo);

    cudaFuncSetAttribute(gemm_tc, cudaFuncAttributeMaxDynamicSharedMemorySize, GT_SMEM);
    cudaFuncSetAttribute(attn_mma, cudaFuncAttributeMaxDynamicSharedMemorySize, AT_SMEM);

    int n4_act = (M_TOK * DIM) / 4;
    const float qscale = 0.08838834764831845f;   // 1/sqrt(128)

    round_kernel<<<(n4_act + 255) / 256, 256>>>(enc, eh, n4_act);
    round_kernel<<<(n4_act + 255) / 256, 256>>>(dec, dh, n4_act);
    roundT_kernel<<<dim3(TWO_DIM / 32, DIM / 32), 256>>>(Wkv, wkv, DIM, TWO_DIM);
    roundT_kernel<<<dim3(DIM / 32,     DIM / 32), 256>>>(Wq,  wq,  DIM, DIM);
    roundT_kernel<<<dim3(DIM / 32,     DIM / 32), 256>>>(Wo,  wo,  DIM, DIM);

    // KV projection -> single fp16 (mode 2)
    gemm_tc<<<dim3(TWO_DIM / 128, M_TOK / 128), 256, GT_SMEM>>>(
        eh, wkv, bkv, 1.0f, nullptr, kv, nullptr, 2, M_TOK, TWO_DIM, DIM);
    // Q projection -> fp16 hi/lo, pre-scaled (mode 1)
    gemm_tc<<<dim3(DIM / 128, M_TOK / 128), 256, GT_SMEM>>>(
        dh, wq, bq, qscale, nullptr, qh, ql, 1, M_TOK, DIM, DIM);

    // attention -> single fp16
    attn_mma<<<dim3(SEQT / 128, NH, BATCH), 256, AT_SMEM>>>(qh, ql, kv, ao);

    // O projection -> fp32 out (mode 0)
    gemm_tc<<<dim3(DIM / 128, M_TOK / 128), 256, GT_SMEM>>>(
        ao, wo, bo, 1.0f, out, nullptr, nullptr, 0, M_TOK, DIM, DIM);
}